// round 1
// baseline (speedup 1.0000x reference)
#include <cuda_runtime.h>
#include <math.h>

#define NN 50000
#define NE 800000
#define FIN 128
#define HC 256
#define NG 64
#define NCLS 16

// ---------------- device scratch (static, allowed) ----------------
__device__ float g_h[(size_t)NN * HC];      // fastkan output / GAT features
__device__ float g_act[(size_t)NN * HC];    // layer activation (silu output)
__device__ float g_as[NN * 4];
__device__ float g_ad[NN * 4];
__device__ int   g_cnt[NN];
__device__ int   g_indptr[NN + 1];
__device__ int   g_cursor[NN];
__device__ int   g_ssrc[NE + NN];           // CSR by dst, self-loop first
__device__ float g_pooled[NG * HC];
__device__ float g_Wt[1024 * 256];          // transposed W (K-major)

// ---------------- small utility kernels ----------------
__global__ void clear_cnt_kernel() {
    int i = blockIdx.x * blockDim.x + threadIdx.x;
    if (i < NN) g_cnt[i] = 0;
}
__global__ void clear_pooled_kernel() {
    int i = blockIdx.x * blockDim.x + threadIdx.x;
    if (i < NG * HC) g_pooled[i] = 0.f;
}
__global__ void hist_kernel(const int* __restrict__ ei) {
    int e = blockIdx.x * blockDim.x + threadIdx.x;
    if (e < NE) atomicAdd(&g_cnt[ei[NE + e]], 1);
}
__global__ void scan_kernel() {
    __shared__ int sm[1024];
    __shared__ int carry_s;
    int t = threadIdx.x;
    if (t == 0) carry_s = 0;
    __syncthreads();
    for (int base = 0; base < NN; base += 1024) {
        int idx = base + t;
        int v = (idx < NN) ? (g_cnt[idx] + 1) : 0;  // +1 self loop
        sm[t] = v;
        __syncthreads();
        for (int off = 1; off < 1024; off <<= 1) {
            int add = (t >= off) ? sm[t - off] : 0;
            __syncthreads();
            sm[t] += add;
            __syncthreads();
        }
        if (idx < NN) g_indptr[idx] = carry_s + sm[t] - v;  // exclusive
        __syncthreads();
        if (t == 1023) carry_s += sm[1023];
        __syncthreads();
    }
    if (t == 0) g_indptr[NN] = carry_s;
}
__global__ void init_cursor_kernel() {
    int i = blockIdx.x * blockDim.x + threadIdx.x;
    if (i < NN) {
        int p = g_indptr[i];
        g_ssrc[p] = i;          // self loop slot
        g_cursor[i] = p + 1;
    }
}
__global__ void scatter_kernel(const int* __restrict__ ei) {
    int e = blockIdx.x * blockDim.x + threadIdx.x;
    if (e < NE) {
        int s = ei[e];
        int d = ei[NE + e];
        int p = atomicAdd(&g_cursor[d], 1);
        g_ssrc[p] = s;
    }
}
__global__ void transpose_kernel(const float* __restrict__ W, int K) {
    int idx = blockIdx.x * blockDim.x + threadIdx.x;
    if (idx < 256 * K) {
        int o = idx / K, k = idx % K;
        g_Wt[k * 256 + o] = W[idx];
    }
}

// ---------------- fused FastKAN GEMM ----------------
// out[m, o] = sum_{d,g} exp(-(((ln(x[m,d]) - c_g) * 0.75)^2)) * Wt[d*4+g, o]
// BM=64, BN=256, BK=16, 256 threads, 8x8 per-thread tile.
template <int D>
__global__ void __launch_bounds__(256, 2)
fastkan_gemm(const float* __restrict__ X,
             const float* __restrict__ lng, const float* __restrict__ lnb,
             const float* __restrict__ Wt, float* __restrict__ out)
{
    const int K = D * 4;
    __shared__ float As[16][65];
    __shared__ float Bs[16][256];
    __shared__ float meanS[64], rstdS[64];
    __shared__ float red[64][8];

    int t = threadIdx.x;
    int m0 = blockIdx.x * 64;

    // ---- per-row mean / rstd ----
    {
        int r = t >> 2, q = t & 3;
        float s = 0.f, ss = 0.f;
        int row = m0 + r;
        if (row < NN) {
            const float* xr = X + (size_t)row * D;
            for (int d = q; d < D; d += 4) { float v = xr[d]; s += v; ss += v * v; }
        }
        red[r][q] = s; red[r][q + 4] = ss;
    }
    __syncthreads();
    if (t < 64) {
        float s  = red[t][0] + red[t][1] + red[t][2] + red[t][3];
        float ss = red[t][4] + red[t][5] + red[t][6] + red[t][7];
        float mean = s / (float)D;
        float var  = ss / (float)D - mean * mean;
        meanS[t] = mean;
        rstdS[t] = rsqrtf(var + 1e-5f);
    }
    __syncthreads();

    int tx = t & 31, ty = t >> 5;
    float acc[8][8];
#pragma unroll
    for (int i = 0; i < 8; i++)
#pragma unroll
        for (int j = 0; j < 8; j++) acc[i][j] = 0.f;

    const int r_fill = t >> 2;   // row within tile for A fill
    const int dq     = t & 3;    // which of 4 d-values in this K-chunk

    for (int k0 = 0; k0 < K; k0 += 16) {
        // B tile: contiguous copy of 4096 floats from Wt + k0*256
        {
            const float4* src = reinterpret_cast<const float4*>(Wt + (size_t)k0 * 256);
            float4* dst = reinterpret_cast<float4*>(&Bs[0][0]);
#pragma unroll
            for (int i = 0; i < 4; i++) dst[t + i * 256] = src[t + i * 256];
        }
        // A tile: compute layernorm + 4 RBF basis values
        {
            int d = (k0 >> 2) + dq;
            int row = m0 + r_fill;
            float v = (row < NN) ? X[(size_t)row * D + d] : 0.f;
            float ln = (v - meanS[r_fill]) * rstdS[r_fill] * lng[d] + lnb[d];
#pragma unroll
            for (int gi = 0; gi < 4; gi++) {
                float c = -2.f + (float)gi * (4.f / 3.f);
                float tt = (ln - c) * 0.75f;
                As[dq * 4 + gi][r_fill] = __expf(-tt * tt);
            }
        }
        __syncthreads();
#pragma unroll
        for (int kk = 0; kk < 16; kk++) {
            float a[8], bb[8];
#pragma unroll
            for (int i = 0; i < 8; i++) a[i] = As[kk][ty * 8 + i];
#pragma unroll
            for (int j = 0; j < 8; j++) bb[j] = Bs[kk][tx * 8 + j];
#pragma unroll
            for (int i = 0; i < 8; i++)
#pragma unroll
                for (int j = 0; j < 8; j++) acc[i][j] += a[i] * bb[j];
        }
        __syncthreads();
    }

    // epilogue: store h
#pragma unroll
    for (int i = 0; i < 8; i++) {
        int row = m0 + ty * 8 + i;
        if (row < NN) {
            float4 v0 = make_float4(acc[i][0], acc[i][1], acc[i][2], acc[i][3]);
            float4 v1 = make_float4(acc[i][4], acc[i][5], acc[i][6], acc[i][7]);
            float* op = out + (size_t)row * 256 + tx * 8;
            *reinterpret_cast<float4*>(op)     = v0;
            *reinterpret_cast<float4*>(op + 4) = v1;
        }
    }
}

// ---------------- attention alphas ----------------
__global__ void alphas_kernel(const float* __restrict__ h,
                              const float* __restrict__ asrc,
                              const float* __restrict__ adst)
{
    int warp = (blockIdx.x * blockDim.x + threadIdx.x) >> 5;
    int lane = threadIdx.x & 31;
    if (warp >= NN) return;
    int head = lane >> 3;
    int cb = head * 64 + (lane & 7) * 8;   // channel base within att arrays
    const float* hp = h + (size_t)warp * 256 + lane * 8;
    float4 v0 = *reinterpret_cast<const float4*>(hp);
    float4 v1 = *reinterpret_cast<const float4*>(hp + 4);
    const float* as = asrc + cb;
    const float* ad = adst + cb;
    float s = v0.x*as[0] + v0.y*as[1] + v0.z*as[2] + v0.w*as[3]
            + v1.x*as[4] + v1.y*as[5] + v1.z*as[6] + v1.w*as[7];
    float d = v0.x*ad[0] + v0.y*ad[1] + v0.z*ad[2] + v0.w*ad[3]
            + v1.x*ad[4] + v1.y*ad[5] + v1.z*ad[6] + v1.w*ad[7];
#pragma unroll
    for (int off = 4; off > 0; off >>= 1) {
        s += __shfl_down_sync(0xffffffffu, s, off, 8);
        d += __shfl_down_sync(0xffffffffu, d, off, 8);
    }
    if ((lane & 7) == 0) {
        g_as[warp * 4 + head] = s;
        g_ad[warp * 4 + head] = d;
    }
}

// ---------------- edge aggregation (warp per dst node) ----------------
__device__ __forceinline__ float leaky(float x) { return x > 0.f ? x : 0.2f * x; }

__global__ void aggregate_kernel(const float* __restrict__ h,
                                 const float* __restrict__ bias,
                                 float* __restrict__ out)
{
    int warp = (blockIdx.x * blockDim.x + threadIdx.x) >> 5;
    int lane = threadIdx.x & 31;
    if (warp >= NN) return;
    int i = warp;
    int p0 = g_indptr[i];
    int p1 = g_indptr[i + 1];
    float4 ad = *reinterpret_cast<const float4*>(&g_ad[i * 4]);

    // pass 1: per-head max (lanes parallel over edges)
    float m0 = -1e30f, m1 = -1e30f, m2 = -1e30f, m3 = -1e30f;
    for (int j = p0 + lane; j < p1; j += 32) {
        int s = g_ssrc[j];
        float4 as = *reinterpret_cast<const float4*>(&g_as[s * 4]);
        m0 = fmaxf(m0, leaky(as.x + ad.x));
        m1 = fmaxf(m1, leaky(as.y + ad.y));
        m2 = fmaxf(m2, leaky(as.z + ad.z));
        m3 = fmaxf(m3, leaky(as.w + ad.w));
    }
#pragma unroll
    for (int off = 16; off > 0; off >>= 1) {
        m0 = fmaxf(m0, __shfl_xor_sync(0xffffffffu, m0, off));
        m1 = fmaxf(m1, __shfl_xor_sync(0xffffffffu, m1, off));
        m2 = fmaxf(m2, __shfl_xor_sync(0xffffffffu, m2, off));
        m3 = fmaxf(m3, __shfl_xor_sync(0xffffffffu, m3, off));
    }

    int head = lane >> 3;
    float mh  = (head == 0) ? m0 : (head == 1) ? m1 : (head == 2) ? m2 : m3;
    float adh = (head == 0) ? ad.x : (head == 1) ? ad.y : (head == 2) ? ad.z : ad.w;

    // pass 2: weighted accumulation (whole warp per edge, lane owns 8 channels)
    float acc[8];
#pragma unroll
    for (int k = 0; k < 8; k++) acc[k] = 0.f;
    float den = 0.f;
    for (int j = p0; j < p1; j++) {
        int s = g_ssrc[j];
        float e = leaky(g_as[s * 4 + head] + adh);
        float w = __expf(e - mh);
        den += w;
        const float* hp = h + (size_t)s * 256 + lane * 8;
        float4 v0 = *reinterpret_cast<const float4*>(hp);
        float4 v1 = *reinterpret_cast<const float4*>(hp + 4);
        acc[0] += w * v0.x; acc[1] += w * v0.y; acc[2] += w * v0.z; acc[3] += w * v0.w;
        acc[4] += w * v1.x; acc[5] += w * v1.y; acc[6] += w * v1.z; acc[7] += w * v1.w;
    }
    float inv = 1.f / den;
    int cb = lane * 8;
    float r[8];
#pragma unroll
    for (int k = 0; k < 8; k++) {
        float v = acc[k] * inv + bias[cb + k];
        r[k] = v / (1.f + __expf(-v));   // silu
    }
    float* op = out + (size_t)i * 256 + cb;
    *reinterpret_cast<float4*>(op)     = make_float4(r[0], r[1], r[2], r[3]);
    *reinterpret_cast<float4*>(op + 4) = make_float4(r[4], r[5], r[6], r[7]);
}

// ---------------- pooling (batch is sorted -> contiguous segments) ----------------
__global__ void pool_kernel(const float* __restrict__ x, const int* __restrict__ batch)
{
    int t = threadIdx.x;           // channel
    int n0 = blockIdx.x * 256;
    if (n0 >= NN) return;
    int n1 = min(n0 + 256, NN);
    float acc = 0.f;
    int cur = batch[n0];
    for (int n = n0; n < n1; n++) {
        int b = batch[n];
        if (b != cur) {
            atomicAdd(&g_pooled[cur * 256 + t], acc);
            acc = 0.f; cur = b;
        }
        acc += x[(size_t)n * 256 + t];
    }
    atomicAdd(&g_pooled[cur * 256 + t], acc);
}

// ---------------- readout: FastKAN (HC->16) + log_softmax ----------------
__global__ void readout_kernel(const float* __restrict__ lng, const float* __restrict__ lnb,
                               const float* __restrict__ Wr, float* __restrict__ out)
{
    __shared__ float bas[1024];
    __shared__ float red[16];
    __shared__ float logit[16];
    __shared__ float mean_s, rstd_s;
    int gidx = blockIdx.x, t = threadIdx.x;
    int lane = t & 31, w = t >> 5;

    float v = g_pooled[gidx * 256 + t];
    float s = v, ss = v * v;
#pragma unroll
    for (int off = 16; off > 0; off >>= 1) {
        s  += __shfl_xor_sync(0xffffffffu, s, off);
        ss += __shfl_xor_sync(0xffffffffu, ss, off);
    }
    if (lane == 0) { red[w] = s; red[8 + w] = ss; }
    __syncthreads();
    if (t == 0) {
        float S = 0.f, SS = 0.f;
        for (int k = 0; k < 8; k++) { S += red[k]; SS += red[8 + k]; }
        float mean = S / 256.f;
        float var  = SS / 256.f - mean * mean;
        mean_s = mean; rstd_s = rsqrtf(var + 1e-5f);
    }
    __syncthreads();
    float ln = (v - mean_s) * rstd_s * lng[t] + lnb[t];
#pragma unroll
    for (int gi = 0; gi < 4; gi++) {
        float c = -2.f + (float)gi * (4.f / 3.f);
        float tt = (ln - c) * 0.75f;
        bas[t * 4 + gi] = __expf(-tt * tt);
    }
    __syncthreads();

    // 8 warps x 2 outputs
    float p0 = 0.f, p1 = 0.f;
    const float* w0 = Wr + (size_t)(2 * w) * 1024;
    const float* w1 = w0 + 1024;
    for (int k = lane; k < 1024; k += 32) {
        float bv = bas[k];
        p0 += bv * w0[k];
        p1 += bv * w1[k];
    }
#pragma unroll
    for (int off = 16; off > 0; off >>= 1) {
        p0 += __shfl_xor_sync(0xffffffffu, p0, off);
        p1 += __shfl_xor_sync(0xffffffffu, p1, off);
    }
    if (lane == 0) { logit[2 * w] = p0; logit[2 * w + 1] = p1; }
    __syncthreads();

    if (t < 32) {
        float l = (lane < 16) ? logit[lane] : -1e30f;
        float m = l;
#pragma unroll
        for (int off = 16; off > 0; off >>= 1)
            m = fmaxf(m, __shfl_xor_sync(0xffffffffu, m, off));
        float ex = (lane < 16) ? __expf(l - m) : 0.f;
        float sum = ex;
#pragma unroll
        for (int off = 16; off > 0; off >>= 1)
            sum += __shfl_xor_sync(0xffffffffu, sum, off);
        if (lane < 16) out[gidx * 16 + lane] = l - m - logf(sum);
    }
}

// ---------------- launch ----------------
extern "C" void kernel_launch(void* const* d_in, const int* in_sizes, int n_in,
                              void* d_out, int out_size)
{
    const float* x     = (const float*)d_in[0];
    const int*   ei    = (const int*)  d_in[1];
    const int*   batch = (const int*)  d_in[2];
    const float* lng0  = (const float*)d_in[3];
    const float* lnb0  = (const float*)d_in[4];
    const float* W0    = (const float*)d_in[5];
    const float* as0   = (const float*)d_in[6];
    const float* ad0   = (const float*)d_in[7];
    const float* b0    = (const float*)d_in[8];
    const float* lng1  = (const float*)d_in[9];
    const float* lnb1  = (const float*)d_in[10];
    const float* W1    = (const float*)d_in[11];
    const float* as1   = (const float*)d_in[12];
    const float* ad1   = (const float*)d_in[13];
    const float* b1    = (const float*)d_in[14];
    const float* lngr  = (const float*)d_in[15];
    const float* lnbr  = (const float*)d_in[16];
    const float* Wr    = (const float*)d_in[17];
    float* out = (float*)d_out;

    float *h_p, *act_p, *wt_p;
    cudaGetSymbolAddress((void**)&h_p,   g_h);
    cudaGetSymbolAddress((void**)&act_p, g_act);
    cudaGetSymbolAddress((void**)&wt_p,  g_Wt);

    const int TPB = 256;
    int gemm_blocks  = (NN + 63) / 64;          // 782
    int warp_blocks  = (NN * 32 + TPB - 1) / TPB;

    clear_cnt_kernel<<<(NN + TPB - 1) / TPB, TPB>>>();
    clear_pooled_kernel<<<(NG * HC + TPB - 1) / TPB, TPB>>>();
    hist_kernel<<<(NE + TPB - 1) / TPB, TPB>>>(ei);
    scan_kernel<<<1, 1024>>>();
    init_cursor_kernel<<<(NN + TPB - 1) / TPB, TPB>>>();
    scatter_kernel<<<(NE + TPB - 1) / TPB, TPB>>>(ei);

    // ---- layer 0 ----
    transpose_kernel<<<(256 * 512 + TPB - 1) / TPB, TPB>>>(W0, 512);
    fastkan_gemm<128><<<gemm_blocks, TPB>>>(x, lng0, lnb0, wt_p, h_p);
    alphas_kernel<<<warp_blocks, TPB>>>(h_p, as0, ad0);
    aggregate_kernel<<<warp_blocks, TPB>>>(h_p, b0, act_p);

    // ---- layer 1 ----
    transpose_kernel<<<(256 * 1024 + TPB - 1) / TPB, TPB>>>(W1, 1024);
    fastkan_gemm<256><<<gemm_blocks, TPB>>>(act_p, lng1, lnb1, wt_p, h_p);
    alphas_kernel<<<warp_blocks, TPB>>>(h_p, as1, ad1);
    aggregate_kernel<<<warp_blocks, TPB>>>(h_p, b1, act_p);

    // ---- readout ----
    pool_kernel<<<(NN + 255) / 256, 256>>>(act_p, batch);
    readout_kernel<<<NG, 256>>>(lngr, lnbr, Wr, out);
}

// round 2
// speedup vs baseline: 2.0435x; 2.0435x over previous
#include <cuda_runtime.h>
#include <math.h>

#define NN 50000
#define NE 800000
#define HC 256
#define NG 64

// ---------------- device scratch ----------------
__device__ float g_h[(size_t)NN * HC];         // fastkan output / GAT features
__device__ float g_act[(size_t)NN * HC];       // layer activation (silu output)
__device__ float g_ln[(size_t)50176 * 256];    // layernormed input (padded rows)
__device__ float g_as[NN * 4];
__device__ float g_ad[NN * 4];
__device__ int   g_cnt[NN];
__device__ int   g_indptr[NN + 1];
__device__ int   g_cursor[NN];
__device__ int   g_ssrc[NE + NN];              // CSR by dst, self-loop first
__device__ float g_pooled[NG * HC];
__device__ float g_Wt[1024 * 256];             // transposed W, tf32-rounded
__device__ int   g_bsum[64];
__device__ int   g_boff[64];

__device__ __forceinline__ float to_tf32(float x) {
    unsigned u;
    asm("cvt.rna.tf32.f32 %0, %1;" : "=r"(u) : "f"(x));
    return __uint_as_float(u);
}

// ---------------- CSR build ----------------
__global__ void clear_kernel() {
    int i = blockIdx.x * blockDim.x + threadIdx.x;
    if (i < NN) g_cnt[i] = 0;
    if (i < NG * HC) g_pooled[i] = 0.f;
}
__global__ void hist_kernel(const int* __restrict__ ei) {
    int e = blockIdx.x * blockDim.x + threadIdx.x;
    if (e < NE) atomicAdd(&g_cnt[ei[NE + e]], 1);
}
// block-scan part 1: 49 blocks x 256 threads x 4 elems
__global__ void scan_part1() {
    __shared__ int wsum[8];
    int t = threadIdx.x;
    int base = blockIdx.x * 1024 + t * 4;
    int v[4];
#pragma unroll
    for (int j = 0; j < 4; j++) {
        int idx = base + j;
        v[j] = (idx < NN) ? (g_cnt[idx] + 1) : 0;   // +1 self loop
    }
    int s = v[0] + v[1] + v[2] + v[3];
    int lane = t & 31, w = t >> 5;
    int sc = s;
#pragma unroll
    for (int off = 1; off < 32; off <<= 1) {
        int u = __shfl_up_sync(0xffffffffu, sc, off);
        if (lane >= off) sc += u;
    }
    if (lane == 31) wsum[w] = sc;
    __syncthreads();
    if (t < 8) {
        int ws = wsum[t];
#pragma unroll
        for (int off = 1; off < 8; off <<= 1) {
            int u = __shfl_up_sync(0x000000ffu, ws, off);
            if (t >= off) ws += u;
        }
        wsum[t] = ws;
    }
    __syncthreads();
    int excl = sc - s + (w > 0 ? wsum[w - 1] : 0);
#pragma unroll
    for (int j = 0; j < 4; j++) {
        int idx = base + j;
        if (idx < NN) g_indptr[idx] = excl;
        excl += v[j];
    }
    if (t == 0) g_bsum[blockIdx.x] = 0;  // will be overwritten below
    __syncthreads();
    if (t == 255) g_bsum[blockIdx.x] = wsum[7];
}
__global__ void scan_part2(int nb) {
    __shared__ int w0tot;
    int t = threadIdx.x;
    int v = (t < nb) ? g_bsum[t] : 0;
    int lane = t & 31, w = t >> 5;
    int sc = v;
#pragma unroll
    for (int off = 1; off < 32; off <<= 1) {
        int u = __shfl_up_sync(0xffffffffu, sc, off);
        if (lane >= off) sc += u;
    }
    if (t == 31) w0tot = sc;
    __syncthreads();
    int incl = sc + (w == 1 ? w0tot : 0);
    g_boff[t] = incl - v;
    if (t == 63) g_indptr[NN] = incl;
}
__global__ void scan_part3() {
    int i = blockIdx.x * 1024 + threadIdx.x;
    if (i < NN) g_indptr[i] += g_boff[blockIdx.x];
}
__global__ void init_cursor_kernel() {
    int i = blockIdx.x * blockDim.x + threadIdx.x;
    if (i < NN) {
        int p = g_indptr[i];
        g_ssrc[p] = i;
        g_cursor[i] = p + 1;
    }
}
__global__ void scatter_kernel(const int* __restrict__ ei) {
    int e = blockIdx.x * blockDim.x + threadIdx.x;
    if (e < NE) {
        int s = ei[e];
        int d = ei[NE + e];
        int p = atomicAdd(&g_cursor[d], 1);
        g_ssrc[p] = s;
    }
}
__global__ void transpose_kernel(const float* __restrict__ W, int K) {
    int idx = blockIdx.x * blockDim.x + threadIdx.x;
    if (idx < 256 * K) {
        int o = idx / K, k = idx % K;
        g_Wt[k * 256 + o] = to_tf32(W[o * K + k]);
    }
}

// ---------------- LayerNorm precompute (warp per row) ----------------
template <int D>
__global__ void ln_kernel(const float* __restrict__ X, const float* __restrict__ g,
                          const float* __restrict__ b, float* __restrict__ out)
{
    int warp = (blockIdx.x * blockDim.x + threadIdx.x) >> 5;
    int lane = threadIdx.x & 31;
    if (warp >= NN) return;
    const float* xr = X + (size_t)warp * D;
    const int V = D / 128;   // float4 per lane
    float4 v[V];
    float s = 0.f, ss = 0.f;
#pragma unroll
    for (int i = 0; i < V; i++) {
        v[i] = *reinterpret_cast<const float4*>(&xr[lane * 4 + i * 128]);
        s  += v[i].x + v[i].y + v[i].z + v[i].w;
        ss += v[i].x*v[i].x + v[i].y*v[i].y + v[i].z*v[i].z + v[i].w*v[i].w;
    }
#pragma unroll
    for (int off = 16; off > 0; off >>= 1) {
        s  += __shfl_xor_sync(0xffffffffu, s, off);
        ss += __shfl_xor_sync(0xffffffffu, ss, off);
    }
    float mean = s / (float)D;
    float rstd = rsqrtf(ss / (float)D - mean * mean + 1e-5f);
    float* orow = out + (size_t)warp * D;
#pragma unroll
    for (int i = 0; i < V; i++) {
        int d = lane * 4 + i * 128;
        float4 gg = *reinterpret_cast<const float4*>(&g[d]);
        float4 bb = *reinterpret_cast<const float4*>(&b[d]);
        float4 o;
        o.x = (v[i].x - mean) * rstd * gg.x + bb.x;
        o.y = (v[i].y - mean) * rstd * gg.y + bb.y;
        o.z = (v[i].z - mean) * rstd * gg.z + bb.z;
        o.w = (v[i].w - mean) * rstd * gg.w + bb.w;
        *reinterpret_cast<float4*>(&orow[d]) = o;
    }
}

// ---------------- tf32 tensor-core FastKAN GEMM ----------------
// out[m,n] = sum_{d,g} basis(LN[m,d], g) * Wt[d*4+g, n]
// BM=128 BN=128 BK=32, 256 threads, warp tile 32x64 (2x8 m16n8k8 tiles)
__device__ __forceinline__ void mma_tf32(float c[4], const unsigned a[4], const unsigned b[2]) {
    asm volatile(
        "mma.sync.aligned.m16n8k8.row.col.f32.tf32.tf32.f32 "
        "{%0,%1,%2,%3}, {%4,%5,%6,%7}, {%8,%9}, {%0,%1,%2,%3};\n"
        : "+f"(c[0]), "+f"(c[1]), "+f"(c[2]), "+f"(c[3])
        : "r"(a[0]), "r"(a[1]), "r"(a[2]), "r"(a[3]), "r"(b[0]), "r"(b[1]));
}

template <int D>
__global__ void __launch_bounds__(256, 2)
kan_mma(const float* __restrict__ LN, const float* __restrict__ Wt, float* __restrict__ out)
{
    __shared__ float As[32][136];   // [k][m]
    __shared__ float Bs[32][136];   // [k][n]

    const int t = threadIdx.x;
    const int wid = t >> 5, lane = t & 31;
    const int wm = wid & 3, wn = wid >> 2;
    const int g4 = lane >> 2, tg = lane & 3;
    const int m0 = blockIdx.x * 128;
    const int n0 = blockIdx.y * 128;
    const int K = 4 * D;

    float c[2][8][4];
#pragma unroll
    for (int mt = 0; mt < 2; mt++)
#pragma unroll
        for (int nt = 0; nt < 8; nt++)
#pragma unroll
            for (int i = 0; i < 4; i++) c[mt][nt][i] = 0.f;

    const int a_row = t & 127;     // tile row this thread fills
    const int a_dh  = t >> 7;      // which half of the 8 d-values

    for (int k0 = 0; k0 < K; k0 += 32) {
        const int d0 = k0 >> 2;
        // B tile (already tf32-rounded in Wt)
#pragma unroll
        for (int i = 0; i < 4; i++) {
            int idx = t + i * 256;
            int kk = idx >> 5;
            int nn = (idx & 31) << 2;
            float4 v = *reinterpret_cast<const float4*>(&Wt[(size_t)(k0 + kk) * 256 + n0 + nn]);
            *reinterpret_cast<float4*>(&Bs[kk][nn]) = v;
        }
        // A tile: RBF basis from LN values
        {
            const float* lp = &LN[(size_t)(m0 + a_row) * D + d0 + a_dh * 4];
            float4 lv = *reinterpret_cast<const float4*>(lp);
            float lvv[4] = {lv.x, lv.y, lv.z, lv.w};
#pragma unroll
            for (int j = 0; j < 4; j++) {
#pragma unroll
                for (int gi = 0; gi < 4; gi++) {
                    float cc = -2.f + (float)gi * (4.f / 3.f);
                    float tt = (lvv[j] - cc) * 0.75f;
                    As[(a_dh * 4 + j) * 4 + gi][a_row] = to_tf32(__expf(-tt * tt));
                }
            }
        }
        __syncthreads();
#pragma unroll
        for (int k8 = 0; k8 < 4; k8++) {
            const int kb = k8 * 8;
            unsigned a[2][4];
#pragma unroll
            for (int mt = 0; mt < 2; mt++) {
                int mr = wm * 32 + mt * 16 + g4;
                a[mt][0] = __float_as_uint(As[kb + tg    ][mr    ]);
                a[mt][1] = __float_as_uint(As[kb + tg    ][mr + 8]);
                a[mt][2] = __float_as_uint(As[kb + tg + 4][mr    ]);
                a[mt][3] = __float_as_uint(As[kb + tg + 4][mr + 8]);
            }
#pragma unroll
            for (int nt = 0; nt < 8; nt++) {
                unsigned b[2];
                int nc = wn * 64 + nt * 8 + g4;
                b[0] = __float_as_uint(Bs[kb + tg    ][nc]);
                b[1] = __float_as_uint(Bs[kb + tg + 4][nc]);
                mma_tf32(c[0][nt], a[0], b);
                mma_tf32(c[1][nt], a[1], b);
            }
        }
        __syncthreads();
    }

    // epilogue
#pragma unroll
    for (int mt = 0; mt < 2; mt++) {
        int r0 = m0 + wm * 32 + mt * 16 + g4;
#pragma unroll
        for (int nt = 0; nt < 8; nt++) {
            int nc = n0 + wn * 64 + nt * 8 + tg * 2;
            if (r0 < NN)
                *reinterpret_cast<float2*>(&out[(size_t)r0 * 256 + nc]) =
                    make_float2(c[mt][nt][0], c[mt][nt][1]);
            if (r0 + 8 < NN)
                *reinterpret_cast<float2*>(&out[(size_t)(r0 + 8) * 256 + nc]) =
                    make_float2(c[mt][nt][2], c[mt][nt][3]);
        }
    }
}

// ---------------- attention alphas ----------------
__global__ void alphas_kernel(const float* __restrict__ h,
                              const float* __restrict__ asrc,
                              const float* __restrict__ adst)
{
    int warp = (blockIdx.x * blockDim.x + threadIdx.x) >> 5;
    int lane = threadIdx.x & 31;
    if (warp >= NN) return;
    int head = lane >> 3;
    int cb = head * 64 + (lane & 7) * 8;
    const float* hp = h + (size_t)warp * 256 + lane * 8;
    float4 v0 = *reinterpret_cast<const float4*>(hp);
    float4 v1 = *reinterpret_cast<const float4*>(hp + 4);
    const float* as = asrc + cb;
    const float* ad = adst + cb;
    float s = v0.x*as[0] + v0.y*as[1] + v0.z*as[2] + v0.w*as[3]
            + v1.x*as[4] + v1.y*as[5] + v1.z*as[6] + v1.w*as[7];
    float d = v0.x*ad[0] + v0.y*ad[1] + v0.z*ad[2] + v0.w*ad[3]
            + v1.x*ad[4] + v1.y*ad[5] + v1.z*ad[6] + v1.w*ad[7];
#pragma unroll
    for (int off = 4; off > 0; off >>= 1) {
        s += __shfl_down_sync(0xffffffffu, s, off, 8);
        d += __shfl_down_sync(0xffffffffu, d, off, 8);
    }
    if ((lane & 7) == 0) {
        g_as[warp * 4 + head] = s;
        g_ad[warp * 4 + head] = d;
    }
}

// ---------------- edge aggregation (warp per dst node) ----------------
__device__ __forceinline__ float leaky(float x) { return x > 0.f ? x : 0.2f * x; }

__global__ void aggregate_kernel(const float* __restrict__ h,
                                 const float* __restrict__ bias,
                                 float* __restrict__ out)
{
    int warp = (blockIdx.x * blockDim.x + threadIdx.x) >> 5;
    int lane = threadIdx.x & 31;
    if (warp >= NN) return;
    int i = warp;
    int p0 = g_indptr[i];
    int p1 = g_indptr[i + 1];
    float4 ad = *reinterpret_cast<const float4*>(&g_ad[i * 4]);

    float m0 = -1e30f, m1 = -1e30f, m2 = -1e30f, m3 = -1e30f;
    for (int j = p0 + lane; j < p1; j += 32) {
        int s = g_ssrc[j];
        float4 as = *reinterpret_cast<const float4*>(&g_as[s * 4]);
        m0 = fmaxf(m0, leaky(as.x + ad.x));
        m1 = fmaxf(m1, leaky(as.y + ad.y));
        m2 = fmaxf(m2, leaky(as.z + ad.z));
        m3 = fmaxf(m3, leaky(as.w + ad.w));
    }
#pragma unroll
    for (int off = 16; off > 0; off >>= 1) {
        m0 = fmaxf(m0, __shfl_xor_sync(0xffffffffu, m0, off));
        m1 = fmaxf(m1, __shfl_xor_sync(0xffffffffu, m1, off));
        m2 = fmaxf(m2, __shfl_xor_sync(0xffffffffu, m2, off));
        m3 = fmaxf(m3, __shfl_xor_sync(0xffffffffu, m3, off));
    }

    int head = lane >> 3;
    float mh  = (head == 0) ? m0 : (head == 1) ? m1 : (head == 2) ? m2 : m3;
    float adh = (head == 0) ? ad.x : (head == 1) ? ad.y : (head == 2) ? ad.z : ad.w;

    float acc[8];
#pragma unroll
    for (int k = 0; k < 8; k++) acc[k] = 0.f;
    float den = 0.f;
    for (int j = p0; j < p1; j++) {
        int s = g_ssrc[j];
        float e = leaky(g_as[s * 4 + head] + adh);
        float w = __expf(e - mh);
        den += w;
        const float* hp = h + (size_t)s * 256 + lane * 8;
        float4 v0 = *reinterpret_cast<const float4*>(hp);
        float4 v1 = *reinterpret_cast<const float4*>(hp + 4);
        acc[0] += w * v0.x; acc[1] += w * v0.y; acc[2] += w * v0.z; acc[3] += w * v0.w;
        acc[4] += w * v1.x; acc[5] += w * v1.y; acc[6] += w * v1.z; acc[7] += w * v1.w;
    }
    float inv = 1.f / den;
    int cb = lane * 8;
    float r[8];
#pragma unroll
    for (int k = 0; k < 8; k++) {
        float v = acc[k] * inv + bias[cb + k];
        r[k] = v / (1.f + __expf(-v));
    }
    float* op = out + (size_t)i * 256 + cb;
    *reinterpret_cast<float4*>(op)     = make_float4(r[0], r[1], r[2], r[3]);
    *reinterpret_cast<float4*>(op + 4) = make_float4(r[4], r[5], r[6], r[7]);
}

// ---------------- pooling ----------------
__global__ void pool_kernel(const float* __restrict__ x, const int* __restrict__ batch)
{
    int t = threadIdx.x;
    int n0 = blockIdx.x * 256;
    if (n0 >= NN) return;
    int n1 = min(n0 + 256, NN);
    float acc = 0.f;
    int cur = batch[n0];
    for (int n = n0; n < n1; n++) {
        int b = batch[n];
        if (b != cur) {
            atomicAdd(&g_pooled[cur * 256 + t], acc);
            acc = 0.f; cur = b;
        }
        acc += x[(size_t)n * 256 + t];
    }
    atomicAdd(&g_pooled[cur * 256 + t], acc);
}

// ---------------- readout ----------------
__global__ void readout_kernel(const float* __restrict__ lng, const float* __restrict__ lnb,
                               const float* __restrict__ Wr, float* __restrict__ out)
{
    __shared__ float bas[1024];
    __shared__ float red[16];
    __shared__ float logit[16];
    __shared__ float mean_s, rstd_s;
    int gidx = blockIdx.x, t = threadIdx.x;
    int lane = t & 31, w = t >> 5;

    float v = g_pooled[gidx * 256 + t];
    float s = v, ss = v * v;
#pragma unroll
    for (int off = 16; off > 0; off >>= 1) {
        s  += __shfl_xor_sync(0xffffffffu, s, off);
        ss += __shfl_xor_sync(0xffffffffu, ss, off);
    }
    if (lane == 0) { red[w] = s; red[8 + w] = ss; }
    __syncthreads();
    if (t == 0) {
        float S = 0.f, SS = 0.f;
        for (int k = 0; k < 8; k++) { S += red[k]; SS += red[8 + k]; }
        float mean = S / 256.f;
        float var  = SS / 256.f - mean * mean;
        mean_s = mean; rstd_s = rsqrtf(var + 1e-5f);
    }
    __syncthreads();
    float ln = (v - mean_s) * rstd_s * lng[t] + lnb[t];
#pragma unroll
    for (int gi = 0; gi < 4; gi++) {
        float cc = -2.f + (float)gi * (4.f / 3.f);
        float tt = (ln - cc) * 0.75f;
        bas[t * 4 + gi] = __expf(-tt * tt);
    }
    __syncthreads();

    float p0 = 0.f, p1 = 0.f;
    const float* w0 = Wr + (size_t)(2 * w) * 1024;
    const float* w1 = w0 + 1024;
    for (int k = lane; k < 1024; k += 32) {
        float bv = bas[k];
        p0 += bv * w0[k];
        p1 += bv * w1[k];
    }
#pragma unroll
    for (int off = 16; off > 0; off >>= 1) {
        p0 += __shfl_xor_sync(0xffffffffu, p0, off);
        p1 += __shfl_xor_sync(0xffffffffu, p1, off);
    }
    if (lane == 0) { logit[2 * w] = p0; logit[2 * w + 1] = p1; }
    __syncthreads();

    if (t < 32) {
        float l = (lane < 16) ? logit[lane] : -1e30f;
        float m = l;
#pragma unroll
        for (int off = 16; off > 0; off >>= 1)
            m = fmaxf(m, __shfl_xor_sync(0xffffffffu, m, off));
        float ex = (lane < 16) ? __expf(l - m) : 0.f;
        float sum = ex;
#pragma unroll
        for (int off = 16; off > 0; off >>= 1)
            sum += __shfl_xor_sync(0xffffffffu, sum, off);
        if (lane < 16) out[gidx * 16 + lane] = l - m - logf(sum);
    }
}

// ---------------- launch ----------------
extern "C" void kernel_launch(void* const* d_in, const int* in_sizes, int n_in,
                              void* d_out, int out_size)
{
    const float* x     = (const float*)d_in[0];
    const int*   ei    = (const int*)  d_in[1];
    const int*   batch = (const int*)  d_in[2];
    const float* lng0  = (const float*)d_in[3];
    const float* lnb0  = (const float*)d_in[4];
    const float* W0    = (const float*)d_in[5];
    const float* as0   = (const float*)d_in[6];
    const float* ad0   = (const float*)d_in[7];
    const float* b0    = (const float*)d_in[8];
    const float* lng1  = (const float*)d_in[9];
    const float* lnb1  = (const float*)d_in[10];
    const float* W1    = (const float*)d_in[11];
    const float* as1   = (const float*)d_in[12];
    const float* ad1   = (const float*)d_in[13];
    const float* b1    = (const float*)d_in[14];
    const float* lngr  = (const float*)d_in[15];
    const float* lnbr  = (const float*)d_in[16];
    const float* Wr    = (const float*)d_in[17];
    float* out = (float*)d_out;

    float *h_p, *act_p, *wt_p, *ln_p;
    cudaGetSymbolAddress((void**)&h_p,   g_h);
    cudaGetSymbolAddress((void**)&act_p, g_act);
    cudaGetSymbolAddress((void**)&wt_p,  g_Wt);
    cudaGetSymbolAddress((void**)&ln_p,  g_ln);

    const int TPB = 256;
    const int scan_blocks = (NN + 1023) / 1024;     // 49
    int warp_blocks = (NN * 32 + TPB - 1) / TPB;
    int ln_blocks   = (NN * 32 + TPB - 1) / TPB;
    dim3 gemm_grid((NN + 127) / 128, 2);

    clear_kernel<<<(NN + TPB - 1) / TPB, TPB>>>();
    hist_kernel<<<(NE + TPB - 1) / TPB, TPB>>>(ei);
    scan_part1<<<scan_blocks, 256>>>();
    scan_part2<<<1, 64>>>(scan_blocks);
    scan_part3<<<scan_blocks, 1024>>>();
    init_cursor_kernel<<<(NN + TPB - 1) / TPB, TPB>>>();
    scatter_kernel<<<(NE + TPB - 1) / TPB, TPB>>>(ei);

    // ---- layer 0 ----
    transpose_kernel<<<(256 * 512 + TPB - 1) / TPB, TPB>>>(W0, 512);
    ln_kernel<128><<<ln_blocks, TPB>>>(x, lng0, lnb0, ln_p);
    kan_mma<128><<<gemm_grid, 256>>>(ln_p, wt_p, h_p);
    alphas_kernel<<<warp_blocks, TPB>>>(h_p, as0, ad0);
    aggregate_kernel<<<warp_blocks, TPB>>>(h_p, b0, act_p);

    // ---- layer 1 ----
    transpose_kernel<<<(256 * 1024 + TPB - 1) / TPB, TPB>>>(W1, 1024);
    ln_kernel<256><<<ln_blocks, TPB>>>(act_p, lng1, lnb1, ln_p);
    kan_mma<256><<<gemm_grid, 256>>>(ln_p, wt_p, h_p);
    alphas_kernel<<<warp_blocks, TPB>>>(h_p, as1, ad1);
    aggregate_kernel<<<warp_blocks, TPB>>>(h_p, b1, act_p);

    // ---- readout ----
    pool_kernel<<<(NN + 255) / 256, 256>>>(act_p, batch);
    readout_kernel<<<NG, 256>>>(lngr, lnbr, Wr, out);
}